// round 1
// baseline (speedup 1.0000x reference)
#include <cuda_runtime.h>
#include <math.h>

// Problem constants
#define Bsz 512
#define Tsz 128
#define Hsz 512
#define Vsz 512
#define G4  (4*Hsz)   // 2048

// ---------------- device scratch (static allocation, allowed) ----------------
__device__ float g_seq0[Bsz*Tsz*Hsz];   // 134 MB : inp, later layer-2 output
__device__ float g_seq1[Bsz*Tsz*Hsz];   // 134 MB : layer-1 output
__device__ float g_xg[Bsz*Tsz*G4];      // 536 MB : precomputed input gates per layer
__device__ float g_hbuf0[Bsz*Hsz];      // ping
__device__ float g_hbuf1[Bsz*Hsz];      // pong
__device__ float g_cst[Bsz*Hsz];        // cell state

// ---------------- embed + condition ----------------
// inp[b,t,h] = emb[trg[b,t],h] + y[b]*yW[h] + yb[h];  trg = [V, x[:, :-1]]
__global__ void embed_kernel(const int* __restrict__ x, const float* __restrict__ y,
                             const float* __restrict__ emb, const float* __restrict__ yW,
                             const float* __restrict__ yb, float* __restrict__ out)
{
    int bt = blockIdx.x;            // 0..B*T-1
    int b = bt / Tsz, t = bt % Tsz;
    int h = threadIdx.x;            // H = 512 threads
    int tok = (t == 0) ? Vsz : x[b*Tsz + (t-1)];
    out[(size_t)bt*Hsz + h] = emb[(size_t)tok*Hsz + h] + y[b]*yW[h] + yb[h];
}

__global__ void zero2_kernel(float* a, float* b, int n)
{
    int i = blockIdx.x*blockDim.x + threadIdx.x;
    if (i < n) { a[i] = 0.f; b[i] = 0.f; }
}

// ---------------- generic fp32 GEMM: C[M,N] = A[M,K] * W[N,K]^T + b1 (+b2) ----
// BM=128, BN=128, BK=16, 256 threads, 8x8 micro-tile per thread.
#define BM 128
#define BN 128
#define BKg 16
__global__ __launch_bounds__(256)
void gemm_bias(const float* __restrict__ A, const float* __restrict__ W,
               const float* __restrict__ b1, const float* __restrict__ b2,
               float* __restrict__ C, int M, int N, int K)
{
    __shared__ float As[BKg][BM];
    __shared__ float Bs[BKg][BN];
    int tid = threadIdx.x;
    int tx = tid & 15, ty = tid >> 4;
    int row0 = blockIdx.y * BM;
    int col0 = blockIdx.x * BN;

    float acc[8][8];
#pragma unroll
    for (int i = 0; i < 8; i++)
#pragma unroll
        for (int j = 0; j < 8; j++) acc[i][j] = 0.f;

    for (int k0 = 0; k0 < K; k0 += BKg) {
#pragma unroll
        for (int i = 0; i < 2; i++) {
            int idx = tid + i*256;          // 0..511
            int r  = idx >> 2;              // 0..127
            int kq = (idx & 3) << 2;        // 0,4,8,12
            float4 v = *(const float4*)(A + (size_t)(row0 + r)*K + k0 + kq);
            As[kq+0][r] = v.x; As[kq+1][r] = v.y; As[kq+2][r] = v.z; As[kq+3][r] = v.w;
            float4 w = *(const float4*)(W + (size_t)(col0 + r)*K + k0 + kq);
            Bs[kq+0][r] = w.x; Bs[kq+1][r] = w.y; Bs[kq+2][r] = w.z; Bs[kq+3][r] = w.w;
        }
        __syncthreads();
#pragma unroll
        for (int kk = 0; kk < BKg; kk++) {
            float a[8], bb[8];
            *(float4*)(a)    = *(const float4*)&As[kk][ty*8];
            *(float4*)(a+4)  = *(const float4*)&As[kk][ty*8+4];
            *(float4*)(bb)   = *(const float4*)&Bs[kk][tx*8];
            *(float4*)(bb+4) = *(const float4*)&Bs[kk][tx*8+4];
#pragma unroll
            for (int i = 0; i < 8; i++)
#pragma unroll
                for (int j = 0; j < 8; j++) acc[i][j] += a[i]*bb[j];
        }
        __syncthreads();
    }

    float bv[8];
#pragma unroll
    for (int j = 0; j < 8; j++) {
        int c = col0 + tx*8 + j;
        float v = b1 ? b1[c] : 0.f;
        if (b2) v += b2[c];
        bv[j] = v;
    }
#pragma unroll
    for (int i = 0; i < 8; i++) {
        size_t off = (size_t)(row0 + ty*8 + i)*N + col0 + tx*8;
        float4 o0, o1;
        o0.x = acc[i][0]+bv[0]; o0.y = acc[i][1]+bv[1];
        o0.z = acc[i][2]+bv[2]; o0.w = acc[i][3]+bv[3];
        o1.x = acc[i][4]+bv[4]; o1.y = acc[i][5]+bv[5];
        o1.z = acc[i][6]+bv[6]; o1.w = acc[i][7]+bv[7];
        *(float4*)(C + off)     = o0;
        *(float4*)(C + off + 4) = o1;
    }
}

// ---------------- fused LSTM step: g = xg_t + h_prev*Whh^T ; gates ; state ---
// Tile: 64 batch rows x 16 u-columns x 4 gates. 256 threads (16x16),
// each thread: 4 batch rows x 1 u x 4 gates = 16 accumulators.
#define TB 64
#define TU 16
#define BKs 32
__global__ __launch_bounds__(256)
void lstm_step(const float* __restrict__ xg, const float* __restrict__ Wh,
               const float* __restrict__ hin, float* __restrict__ hout,
               float* __restrict__ cst, float* __restrict__ seq_out, int t)
{
    __shared__ float Hs[BKs][TB];   // h_prev tile, transposed
    __shared__ float Ws[BKs][64];   // Whh rows: col = gate*16 + u_local
    int tid = threadIdx.x;
    int tx = tid & 15, ty = tid >> 4;
    int u0 = blockIdx.x * TU;
    int b0 = blockIdx.y * TB;

    float acc[4][4];                // [b_sub][gate]
#pragma unroll
    for (int i = 0; i < 4; i++)
#pragma unroll
        for (int g = 0; g < 4; g++) acc[i][g] = 0.f;

    for (int k0 = 0; k0 < Hsz; k0 += BKs) {
#pragma unroll
        for (int i = 0; i < 2; i++) {
            int idx = tid + i*256;          // 0..511
            int r  = idx >> 3;              // 0..63
            int kq = (idx & 7) << 2;        // 0..28
            float4 v = *(const float4*)(hin + (size_t)(b0 + r)*Hsz + k0 + kq);
            Hs[kq+0][r] = v.x; Hs[kq+1][r] = v.y; Hs[kq+2][r] = v.z; Hs[kq+3][r] = v.w;
            int gi = r >> 4, ul = r & 15;   // gate / u_local
            float4 w = *(const float4*)(Wh + (size_t)(gi*Hsz + u0 + ul)*Hsz + k0 + kq);
            Ws[kq+0][r] = w.x; Ws[kq+1][r] = w.y; Ws[kq+2][r] = w.z; Ws[kq+3][r] = w.w;
        }
        __syncthreads();
#pragma unroll
        for (int kk = 0; kk < BKs; kk++) {
            float a[4];
            *(float4*)a = *(const float4*)&Hs[kk][ty*4];
            float w0 = Ws[kk][tx], w1 = Ws[kk][16+tx],
                  w2 = Ws[kk][32+tx], w3 = Ws[kk][48+tx];
#pragma unroll
            for (int i = 0; i < 4; i++) {
                acc[i][0] += a[i]*w0;
                acc[i][1] += a[i]*w1;
                acc[i][2] += a[i]*w2;
                acc[i][3] += a[i]*w3;
            }
        }
        __syncthreads();
    }

    int u = u0 + tx;
#pragma unroll
    for (int i = 0; i < 4; i++) {
        int b = b0 + ty*4 + i;
        size_t xoff = ((size_t)b*Tsz + t)*G4 + u;
        float gi = acc[i][0] + xg[xoff];
        float gf = acc[i][1] + xg[xoff + Hsz];
        float gg = acc[i][2] + xg[xoff + 2*Hsz];
        float go = acc[i][3] + xg[xoff + 3*Hsz];
        float ig = 1.f/(1.f + expf(-gi));
        float fg = 1.f/(1.f + expf(-gf));
        float og = 1.f/(1.f + expf(-go));
        float gt = tanhf(gg);
        int so = b*Hsz + u;
        float cN = fg * cst[so] + ig * gt;
        cst[so] = cN;
        float hN = og * tanhf(cN);
        hout[so] = hN;
        seq_out[((size_t)b*Tsz + t)*Hsz + u] = hN;
    }
}

// ---------------- launch ----------------
extern "C" void kernel_launch(void* const* d_in, const int* in_sizes, int n_in,
                              void* d_out, int out_size)
{
    const int*   x    = (const int*)  d_in[0];
    const float* y    = (const float*)d_in[1];
    const float* emb  = (const float*)d_in[2];
    const float* yW   = (const float*)d_in[3];
    const float* yb   = (const float*)d_in[4];
    const float* Wih  = (const float*)d_in[5];
    const float* Whh  = (const float*)d_in[6];
    const float* bih  = (const float*)d_in[7];
    const float* bhh  = (const float*)d_in[8];
    const float* decW = (const float*)d_in[9];
    const float* decb = (const float*)d_in[10];
    float* out = (float*)d_out;

    float *seq0, *seq1, *xg, *h0, *h1, *c;
    cudaGetSymbolAddress((void**)&seq0, g_seq0);
    cudaGetSymbolAddress((void**)&seq1, g_seq1);
    cudaGetSymbolAddress((void**)&xg,   g_xg);
    cudaGetSymbolAddress((void**)&h0,   g_hbuf0);
    cudaGetSymbolAddress((void**)&h1,   g_hbuf1);
    cudaGetSymbolAddress((void**)&c,    g_cst);
    float* hb[2] = { h0, h1 };

    const int MT = Bsz*Tsz;   // 65536

    // 1. embed + condition -> seq0
    embed_kernel<<<MT, Hsz>>>(x, y, emb, yW, yb, seq0);

    // 2. two LSTM layers
    const float* in_seq  = seq0;
    float*       out_seq = seq1;
    for (int l = 0; l < 2; l++) {
        const float* Wi = Wih + (size_t)l*G4*Hsz;
        const float* Wr = Whh + (size_t)l*G4*Hsz;
        const float* bi = bih + (size_t)l*G4;
        const float* bh = bhh + (size_t)l*G4;

        // xg = in_seq @ Wi^T + bi + bh
        gemm_bias<<<dim3(G4/BN, MT/BM), 256>>>(in_seq, Wi, bi, bh, xg, MT, G4, Hsz);

        // reset state
        zero2_kernel<<<(Bsz*Hsz + 255)/256, 256>>>(hb[0], c, Bsz*Hsz);

        // sequential recurrence, double-buffered h
        for (int t = 0; t < Tsz; t++) {
            lstm_step<<<dim3(Hsz/TU, Bsz/TB), 256>>>(
                xg, Wr, hb[t & 1], hb[(t + 1) & 1], c, out_seq, t);
        }

        // swap sequence buffers for next layer
        const float* tmp_in = out_seq;
        out_seq = (float*)in_seq;
        in_seq  = tmp_in;
    }

    // 3. decoder: logits = h_seq @ decW^T + decb   (h_seq is in in_seq now)
    gemm_bias<<<dim3(Vsz/BN, MT/BM), 256>>>(in_seq, decW, decb, nullptr, out, MT, Vsz, Hsz);
}